// round 4
// baseline (speedup 1.0000x reference)
#include <cuda_runtime.h>
#include <cuda_fp16.h>
#include <math.h>

// HashGrid: 10-level Instant-NGP hash encoding, 2M points, FEAT_DIM=3.
// R3: spatial counting-sort (32^3 cells) so each warp processes spatially
// coherent points -> shared-memory gathers become broadcasts, cutting the
// saturated LDS-crossbar wavefronts (R2 ncu: L1 pipe 89.7%, ~5 wf/gather).
// Codebooks stay fp16-packed in smem (8 B/entry); accumulation fp32.

#define NLOD 10

struct Params { const float* cb[NLOD]; };

__host__ __device__ constexpr int H_SIZES(int l) {
    constexpr int s[NLOD] = {49, 64, 121, 196, 324, 529, 900, 1024, 1024, 1024};
    return s[l];
}
__host__ __device__ constexpr int H_OFFS(int l) {
    constexpr int o[NLOD] = {0, 49, 113, 234, 430, 754, 1283, 2183, 3207, 4231};
    return o[l];
}
constexpr int H_TOTAL = 5255;
constexpr int SMEM_BYTES = H_TOTAL * 8;   // 42,040 bytes (uint2 per entry)
constexpr int THREADS = 512;

// ---- binning scratch (static device globals; no allocation) ----
constexpr int CELL_BITS = 5;                       // 32 cells per axis
constexpr int NCELLS = 1 << (3 * CELL_BITS);       // 32768
constexpr int NMAX = 2 * 1024 * 1024;              // 2,097,152 >= 2,000,000

__device__ unsigned g_hist[NCELLS];
__device__ unsigned g_cursor[NCELLS];
__device__ unsigned g_perm[NMAX];
__device__ float    g_ptss[3 * NMAX];

__device__ __forceinline__ int cell_of(float x, float y, float z) {
    int cx = (int)(x * 32.0f); cx = cx > 31 ? 31 : (cx < 0 ? 0 : cx);
    int cy = (int)(y * 32.0f); cy = cy > 31 ? 31 : (cy < 0 ? 0 : cy);
    int cz = (int)(z * 32.0f); cz = cz > 31 ? 31 : (cz < 0 ? 0 : cz);
    return (cx << (2 * CELL_BITS)) | (cy << CELL_BITS) | cz;
}

__global__ void zero_hist_kernel() {
    int i = blockIdx.x * blockDim.x + threadIdx.x;
    if (i < NCELLS) g_hist[i] = 0u;
}

__global__ void hist_kernel(const float* __restrict__ pts, int n) {
    int stride = gridDim.x * blockDim.x;
    for (int i = blockIdx.x * blockDim.x + threadIdx.x; i < n; i += stride) {
        float x = pts[3 * i], y = pts[3 * i + 1], z = pts[3 * i + 2];
        atomicAdd(&g_hist[cell_of(x, y, z)], 1u);
    }
}

__global__ __launch_bounds__(1024, 1) void scan_kernel() {
    __shared__ unsigned ssum[1024];
    const int tid = threadIdx.x;
    const int per = NCELLS / 1024;  // 32
    unsigned s = 0;
    for (int c = 0; c < per; c++) s += g_hist[tid * per + c];
    ssum[tid] = s;
    __syncthreads();
    // Hillis-Steele inclusive scan
    for (int off = 1; off < 1024; off <<= 1) {
        unsigned v = (tid >= off) ? ssum[tid - off] : 0u;
        __syncthreads();
        ssum[tid] += v;
        __syncthreads();
    }
    unsigned run = (tid == 0) ? 0u : ssum[tid - 1];
    for (int c = 0; c < per; c++) {
        unsigned h = g_hist[tid * per + c];
        g_cursor[tid * per + c] = run;
        run += h;
    }
}

__global__ void scatter_kernel(const float* __restrict__ pts, int n) {
    int stride = gridDim.x * blockDim.x;
    for (int i = blockIdx.x * blockDim.x + threadIdx.x; i < n; i += stride) {
        float x = pts[3 * i], y = pts[3 * i + 1], z = pts[3 * i + 2];
        unsigned slot = atomicAdd(&g_cursor[cell_of(x, y, z)], 1u);
        g_perm[slot] = (unsigned)i;
        g_ptss[3 * slot + 0] = x;
        g_ptss[3 * slot + 1] = y;
        g_ptss[3 * slot + 2] = z;
    }
}

template <int LAST_RES, bool BINNED>
__global__ __launch_bounds__(THREADS, 2)
void hashgrid_kernel(const float* __restrict__ pts, Params prm,
                     float* __restrict__ out, int n)
{
    extern __shared__ uint2 scb[];   // each entry: {half2(f0,f1), half2(f2,0)}

    #pragma unroll
    for (int l = 0; l < NLOD; l++) {
        const float* __restrict__ src = prm.cb[l];
        const int sz = H_SIZES(l);
        const int off = H_OFFS(l);
        for (int i = threadIdx.x; i < sz; i += THREADS) {
            __half2 h01 = __floats2half2_rn(src[3 * i], src[3 * i + 1]);
            __half2 h23 = __floats2half2_rn(src[3 * i + 2], 0.0f);
            uint2 v;
            v.x = *reinterpret_cast<unsigned*>(&h01);
            v.y = *reinterpret_cast<unsigned*>(&h23);
            scb[off + i] = v;
        }
    }
    __syncthreads();

    const float* __restrict__ src_pts = BINNED ? g_ptss : pts;

    const int stride = gridDim.x * THREADS;
    for (int j = blockIdx.x * THREADS + threadIdx.x; j < n; j += stride) {
        const float px = src_pts[3 * j + 0];
        const float py = src_pts[3 * j + 1];
        const float pz = src_pts[3 * j + 2];
        float a0 = 0.0f, a1 = 0.0f, a2 = 0.0f;

        #pragma unroll
        for (int l = 0; l < NLOD; l++) {
            constexpr int RESA[NLOD] = {7, 8, 11, 14, 18, 23, 30, 38, 50, LAST_RES};
            const int R = RESA[l];
            const unsigned S = (unsigned)H_SIZES(l);   // compile-time -> magic mod
            const int O = H_OFFS(l);
            const float scale = (float)(R - 1);

            const float xs = px * scale, ys = py * scale, zs = pz * scale;
            int x0 = (int)xs; x0 = x0 > R - 2 ? R - 2 : x0;
            int y0 = (int)ys; y0 = y0 > R - 2 ? R - 2 : y0;
            int z0 = (int)zs; z0 = z0 > R - 2 ? R - 2 : z0;
            const float wx = xs - (float)x0, wy = ys - (float)y0, wz = zs - (float)z0;
            const float ux = 1.0f - wx, uy = 1.0f - wy, uz = 1.0f - wz;

            const unsigned hx0 = (unsigned)x0;
            const unsigned hx1 = hx0 + 1u;
            const unsigned hy0 = (unsigned)y0 * 2654435761u;
            const unsigned hy1 = hy0 + 2654435761u;
            const unsigned hz0 = (unsigned)z0 * 805459861u;
            const unsigned hz1 = hz0 + 805459861u;

            const float w00 = uy * uz, w01 = uy * wz, w10 = wy * uz, w11 = wy * wz;

            #define HG_CORNER(HX, HY, HZ, WX, WYZ)                           \
            {                                                                \
                const unsigned idx = ((HX) ^ (HY) ^ (HZ)) % S;               \
                const uint2 v = scb[O + (int)idx];                           \
                const __half2 h01 = *reinterpret_cast<const __half2*>(&v.x); \
                const __half  h2  = *reinterpret_cast<const __half*>(&v.y);  \
                const float2 f01 = __half22float2(h01);                      \
                const float  f2  = __half2float(h2);                         \
                const float w = (WX) * (WYZ);                                \
                a0 = fmaf(w, f01.x, a0);                                     \
                a1 = fmaf(w, f01.y, a1);                                     \
                a2 = fmaf(w, f2,    a2);                                     \
            }
            HG_CORNER(hx0, hy0, hz0, ux, w00)
            HG_CORNER(hx0, hy0, hz1, ux, w01)
            HG_CORNER(hx0, hy1, hz0, ux, w10)
            HG_CORNER(hx0, hy1, hz1, ux, w11)
            HG_CORNER(hx1, hy0, hz0, wx, w00)
            HG_CORNER(hx1, hy0, hz1, wx, w01)
            HG_CORNER(hx1, hy1, hz0, wx, w10)
            HG_CORNER(hx1, hy1, hz1, wx, w11)
            #undef HG_CORNER
        }

        const int oi = BINNED ? (int)g_perm[j] : j;
        out[3 * oi + 0] = a0;
        out[3 * oi + 1] = a1;
        out[3 * oi + 2] = a2;
    }
}

template <int LAST_RES>
static void launch_main(bool binned, const float* pts, const Params& prm,
                        float* out, int n, int blocks)
{
    if (binned) {
        cudaFuncSetAttribute(hashgrid_kernel<LAST_RES, true>,
                             cudaFuncAttributeMaxDynamicSharedMemorySize, SMEM_BYTES);
        hashgrid_kernel<LAST_RES, true><<<blocks, THREADS, SMEM_BYTES>>>(pts, prm, out, n);
    } else {
        cudaFuncSetAttribute(hashgrid_kernel<LAST_RES, false>,
                             cudaFuncAttributeMaxDynamicSharedMemorySize, SMEM_BYTES);
        hashgrid_kernel<LAST_RES, false><<<blocks, THREADS, SMEM_BYTES>>>(pts, prm, out, n);
    }
}

extern "C" void kernel_launch(void* const* d_in, const int* in_sizes, int n_in,
                              void* d_out, int out_size)
{
    const float* pts = (const float*)d_in[0];
    const int n = in_sizes[0] / 3;

    Params prm;
    for (int l = 0; l < NLOD; l++) prm.cb[l] = (const float*)d_in[1 + l];

    // Replicate the reference's LOD formula exactly in double precision:
    // 6*b^9 sits within fp noise of exactly 64.0; compute the floor the same
    // way numpy does and dispatch on the result.
    const double b = exp((log(64.0) - log(6.0)) / 9.0);
    const double v9 = 6.0 * pow(b, 9.0);
    const int last_res = (int)(1.0 + floor(v9));

    int sm_count = 0;
    cudaDeviceGetAttribute(&sm_count, cudaDevAttrMultiProcessorCount, 0);
    if (sm_count <= 0) sm_count = 148;
    const int blocks = sm_count * 2;

    float* out = (float*)d_out;
    const bool binned = (n <= NMAX);

    if (binned) {
        zero_hist_kernel<<<(NCELLS + 255) / 256, 256>>>();
        hist_kernel<<<blocks, 256>>>(pts, n);
        scan_kernel<<<1, 1024>>>();
        scatter_kernel<<<blocks, 256>>>(pts, n);
    }

    if (last_res == 65) launch_main<65>(binned, pts, prm, out, n, blocks);
    else                launch_main<64>(binned, pts, prm, out, n, blocks);
}

// round 5
// speedup vs baseline: 1.0001x; 1.0001x over previous
#include <cuda_runtime.h>
#include <cuda_fp16.h>
#include <math.h>

// HashGrid: 10-level Instant-NGP hash encoding, 2M points, FEAT_DIM=3.
// R5: keep R3's spatial counting-sort (32^3 cells -> warp-coherent smem
// broadcasts in the gather kernel) but fix the binning overhead: R4 showed
// scatter at 70us with occ=23.7%/issue=3.3% (latency-bound, MLP=1, grid too
// small). Now 4x-unrolled atomics + 8 CTAs/SM on hist/scatter.

#define NLOD 10

struct Params { const float* cb[NLOD]; };

__host__ __device__ constexpr int H_SIZES(int l) {
    constexpr int s[NLOD] = {49, 64, 121, 196, 324, 529, 900, 1024, 1024, 1024};
    return s[l];
}
__host__ __device__ constexpr int H_OFFS(int l) {
    constexpr int o[NLOD] = {0, 49, 113, 234, 430, 754, 1283, 2183, 3207, 4231};
    return o[l];
}
constexpr int H_TOTAL = 5255;
constexpr int SMEM_BYTES = H_TOTAL * 8;   // 42,040 bytes (uint2 per entry)
constexpr int THREADS = 512;

// ---- binning scratch (static device globals; no allocation) ----
constexpr int CELL_BITS = 5;                       // 32 cells per axis
constexpr int NCELLS = 1 << (3 * CELL_BITS);       // 32768
constexpr int NMAX = 2 * 1024 * 1024;

__device__ unsigned g_hist[NCELLS];
__device__ unsigned g_cursor[NCELLS];
__device__ unsigned g_perm[NMAX];
__device__ float    g_ptss[3 * NMAX];

__device__ __forceinline__ int cell_of(float x, float y, float z) {
    int cx = (int)(x * 32.0f); cx = cx > 31 ? 31 : (cx < 0 ? 0 : cx);
    int cy = (int)(y * 32.0f); cy = cy > 31 ? 31 : (cy < 0 ? 0 : cy);
    int cz = (int)(z * 32.0f); cz = cz > 31 ? 31 : (cz < 0 ? 0 : cz);
    return (cx << (2 * CELL_BITS)) | (cy << CELL_BITS) | cz;
}

__global__ void zero_hist_kernel() {
    int i = blockIdx.x * blockDim.x + threadIdx.x;
    if (i < NCELLS) g_hist[i] = 0u;
}

// 4 independent points per thread per iteration: overlaps the REDG issues.
__global__ __launch_bounds__(256) void hist_kernel(const float* __restrict__ pts, int n) {
    const int tpc = blockDim.x;                 // threads per chunk row
    const int stride = gridDim.x * tpc * 4;
    for (int base = blockIdx.x * tpc * 4 + threadIdx.x; base < n; base += stride) {
        int   idx[4]; bool valid[4];
        float x[4], y[4], z[4];
        #pragma unroll
        for (int u = 0; u < 4; u++) {
            int i = base + u * tpc;
            valid[u] = i < n;
            int ic = valid[u] ? i : 0;
            x[u] = pts[3 * ic]; y[u] = pts[3 * ic + 1]; z[u] = pts[3 * ic + 2];
            idx[u] = cell_of(x[u], y[u], z[u]);
        }
        #pragma unroll
        for (int u = 0; u < 4; u++)
            if (valid[u]) atomicAdd(&g_hist[idx[u]], 1u);   // no use of return -> RED
    }
}

__global__ __launch_bounds__(1024, 1) void scan_kernel() {
    __shared__ unsigned ssum[1024];
    const int tid = threadIdx.x;
    const int per = NCELLS / 1024;  // 32
    unsigned s = 0;
    for (int c = 0; c < per; c++) s += g_hist[tid * per + c];
    ssum[tid] = s;
    __syncthreads();
    for (int off = 1; off < 1024; off <<= 1) {
        unsigned v = (tid >= off) ? ssum[tid - off] : 0u;
        __syncthreads();
        ssum[tid] += v;
        __syncthreads();
    }
    unsigned run = (tid == 0) ? 0u : ssum[tid - 1];
    for (int c = 0; c < per; c++) {
        unsigned h = g_hist[tid * per + c];
        g_cursor[tid * per + c] = run;
        run += h;
    }
}

// 4 independent ATOMG round-trips in flight per thread.
__global__ __launch_bounds__(256) void scatter_kernel(const float* __restrict__ pts, int n) {
    const int tpc = blockDim.x;
    const int stride = gridDim.x * tpc * 4;
    for (int base = blockIdx.x * tpc * 4 + threadIdx.x; base < n; base += stride) {
        int   idx[4]; bool valid[4];
        float x[4], y[4], z[4];
        unsigned slot[4];
        #pragma unroll
        for (int u = 0; u < 4; u++) {
            int i = base + u * tpc;
            valid[u] = i < n;
            int ic = valid[u] ? i : 0;
            x[u] = pts[3 * ic]; y[u] = pts[3 * ic + 1]; z[u] = pts[3 * ic + 2];
            idx[u] = cell_of(x[u], y[u], z[u]);
        }
        #pragma unroll
        for (int u = 0; u < 4; u++)
            if (valid[u]) slot[u] = atomicAdd(&g_cursor[idx[u]], 1u);
        #pragma unroll
        for (int u = 0; u < 4; u++) {
            if (valid[u]) {
                int i = base + u * tpc;
                g_perm[slot[u]] = (unsigned)i;
                g_ptss[3 * slot[u] + 0] = x[u];
                g_ptss[3 * slot[u] + 1] = y[u];
                g_ptss[3 * slot[u] + 2] = z[u];
            }
        }
    }
}

template <int LAST_RES>
__global__ __launch_bounds__(THREADS, 2)
void hashgrid_kernel(Params prm, float* __restrict__ out, int n)
{
    extern __shared__ uint2 scb[];   // each entry: {half2(f0,f1), half2(f2,_)}

    #pragma unroll
    for (int l = 0; l < NLOD; l++) {
        const float* __restrict__ src = prm.cb[l];
        const int sz = H_SIZES(l);
        const int off = H_OFFS(l);
        for (int i = threadIdx.x; i < sz; i += THREADS) {
            __half2 h01 = __floats2half2_rn(src[3 * i], src[3 * i + 1]);
            __half2 h23 = __floats2half2_rn(src[3 * i + 2], 0.0f);
            uint2 v;
            v.x = *reinterpret_cast<unsigned*>(&h01);
            v.y = *reinterpret_cast<unsigned*>(&h23);
            scb[off + i] = v;
        }
    }
    __syncthreads();

    const int stride = gridDim.x * THREADS;
    for (int j = blockIdx.x * THREADS + threadIdx.x; j < n; j += stride) {
        const float px = g_ptss[3 * j + 0];
        const float py = g_ptss[3 * j + 1];
        const float pz = g_ptss[3 * j + 2];
        float a0 = 0.0f, a1 = 0.0f, a2 = 0.0f;

        #pragma unroll
        for (int l = 0; l < NLOD; l++) {
            constexpr int RESA[NLOD] = {7, 8, 11, 14, 18, 23, 30, 38, 50, LAST_RES};
            const int R = RESA[l];
            const unsigned S = (unsigned)H_SIZES(l);   // compile-time -> magic mod
            const int O = H_OFFS(l);
            const float scale = (float)(R - 1);

            const float xs = px * scale, ys = py * scale, zs = pz * scale;
            int x0 = (int)xs; x0 = x0 > R - 2 ? R - 2 : x0;
            int y0 = (int)ys; y0 = y0 > R - 2 ? R - 2 : y0;
            int z0 = (int)zs; z0 = z0 > R - 2 ? R - 2 : z0;
            const float wx = xs - (float)x0, wy = ys - (float)y0, wz = zs - (float)z0;
            const float ux = 1.0f - wx, uy = 1.0f - wy, uz = 1.0f - wz;

            const unsigned hx0 = (unsigned)x0;
            const unsigned hx1 = hx0 + 1u;
            const unsigned hy0 = (unsigned)y0 * 2654435761u;
            const unsigned hy1 = hy0 + 2654435761u;
            const unsigned hz0 = (unsigned)z0 * 805459861u;
            const unsigned hz1 = hz0 + 805459861u;

            const float w00 = uy * uz, w01 = uy * wz, w10 = wy * uz, w11 = wy * wz;

            #define HG_CORNER(HX, HY, HZ, WX, WYZ)                           \
            {                                                                \
                const unsigned idx = ((HX) ^ (HY) ^ (HZ)) % S;               \
                const uint2 v = scb[O + (int)idx];                           \
                const __half2 h01 = *reinterpret_cast<const __half2*>(&v.x); \
                const __half  h2  = *reinterpret_cast<const __half*>(&v.y);  \
                const float2 f01 = __half22float2(h01);                      \
                const float  f2  = __half2float(h2);                         \
                const float w = (WX) * (WYZ);                                \
                a0 = fmaf(w, f01.x, a0);                                     \
                a1 = fmaf(w, f01.y, a1);                                     \
                a2 = fmaf(w, f2,    a2);                                     \
            }
            HG_CORNER(hx0, hy0, hz0, ux, w00)
            HG_CORNER(hx0, hy0, hz1, ux, w01)
            HG_CORNER(hx0, hy1, hz0, ux, w10)
            HG_CORNER(hx0, hy1, hz1, ux, w11)
            HG_CORNER(hx1, hy0, hz0, wx, w00)
            HG_CORNER(hx1, hy0, hz1, wx, w01)
            HG_CORNER(hx1, hy1, hz0, wx, w10)
            HG_CORNER(hx1, hy1, hz1, wx, w11)
            #undef HG_CORNER
        }

        const int oi = (int)g_perm[j];
        out[3 * oi + 0] = a0;
        out[3 * oi + 1] = a1;
        out[3 * oi + 2] = a2;
    }
}

extern "C" void kernel_launch(void* const* d_in, const int* in_sizes, int n_in,
                              void* d_out, int out_size)
{
    const float* pts = (const float*)d_in[0];
    const int n = in_sizes[0] / 3;

    Params prm;
    for (int l = 0; l < NLOD; l++) prm.cb[l] = (const float*)d_in[1 + l];

    // Replicate the reference's LOD formula exactly in double precision:
    // 6*b^9 sits within fp noise of exactly 64.0; compute the floor the same
    // way numpy does and dispatch on the result.
    const double b = exp((log(64.0) - log(6.0)) / 9.0);
    const double v9 = 6.0 * pow(b, 9.0);
    const int last_res = (int)(1.0 + floor(v9));

    int sm_count = 0;
    cudaDeviceGetAttribute(&sm_count, cudaDevAttrMultiProcessorCount, 0);
    if (sm_count <= 0) sm_count = 148;
    const int main_blocks = sm_count * 2;
    const int bin_blocks  = sm_count * 8;   // occupancy for latency-bound atomics

    float* out = (float*)d_out;

    zero_hist_kernel<<<(NCELLS + 255) / 256, 256>>>();
    hist_kernel<<<bin_blocks, 256>>>(pts, n);
    scan_kernel<<<1, 1024>>>();
    scatter_kernel<<<bin_blocks, 256>>>(pts, n);

    if (last_res == 65) {
        cudaFuncSetAttribute(hashgrid_kernel<65>,
                             cudaFuncAttributeMaxDynamicSharedMemorySize, SMEM_BYTES);
        hashgrid_kernel<65><<<main_blocks, THREADS, SMEM_BYTES>>>(prm, out, n);
    } else {
        cudaFuncSetAttribute(hashgrid_kernel<64>,
                             cudaFuncAttributeMaxDynamicSharedMemorySize, SMEM_BYTES);
        hashgrid_kernel<64><<<main_blocks, THREADS, SMEM_BYTES>>>(prm, out, n);
    }
}

// round 8
// speedup vs baseline: 1.0988x; 1.0986x over previous
#include <cuda_runtime.h>
#include <cuda_fp16.h>
#include <math.h>

// HashGrid: 10-level Instant-NGP hash encoding, 2M points, FEAT_DIM=3.
// R7 (= R6 re-run after infra failure, + packed scatter): counting sort with
// NO per-point global atomics (R5: ATOMG-latency-bound). Per-CTA smem
// histogram -> count matrix -> per-cell scan over CTAs -> scatter via smem
// cursors writing ONE uint4 {x,y,z,perm} per point (STG.128). Main gather
// kernel reads the packed buffer coalesced; codebooks fp16-packed in smem.

#define NLOD 10

struct Params { const float* cb[NLOD]; };

__host__ __device__ constexpr int H_SIZES(int l) {
    constexpr int s[NLOD] = {49, 64, 121, 196, 324, 529, 900, 1024, 1024, 1024};
    return s[l];
}
__host__ __device__ constexpr int H_OFFS(int l) {
    constexpr int o[NLOD] = {0, 49, 113, 234, 430, 754, 1283, 2183, 3207, 4231};
    return o[l];
}
constexpr int H_TOTAL = 5255;
constexpr int SMEM_BYTES = H_TOTAL * 8;   // 42,040 B (uint2 per entry)
constexpr int THREADS = 512;

// ---- binning scratch (static device globals; no allocation) ----
constexpr int CELL_BITS = 5;                  // 32 cells/axis
constexpr int NCELLS = 1 << (3 * CELL_BITS);  // 32768
constexpr int NMAX = 2 * 1024 * 1024;
constexpr int GMAX = 160;                     // max CTAs in binning grid
constexpr int BIN_SMEM = NCELLS * 4;          // 131072 B

__device__ unsigned short g_cnt[GMAX * NCELLS];   // counts per (cta, cell)
__device__ unsigned g_offs[GMAX * NCELLS];        // excl prefix over ctas, per cell
__device__ unsigned g_totals[NCELLS];
__device__ unsigned g_base[NCELLS];               // excl prefix over cells
__device__ uint4    g_sorted[NMAX];               // {x,y,z bits, original index}

__device__ __forceinline__ int cell_of(float x, float y, float z) {
    int cx = (int)(x * 32.0f); cx = cx > 31 ? 31 : (cx < 0 ? 0 : cx);
    int cy = (int)(y * 32.0f); cy = cy > 31 ? 31 : (cy < 0 ? 0 : cy);
    int cz = (int)(z * 32.0f); cz = cz > 31 ? 31 : (cz < 0 ? 0 : cz);
    return (cx << (2 * CELL_BITS)) | (cy << CELL_BITS) | cz;
}

// Per-CTA smem histogram of a contiguous chunk; plain stores to count matrix.
__global__ __launch_bounds__(1024, 1)
void hist_smem_kernel(const float* __restrict__ pts, int n, int chunk) {
    extern __shared__ unsigned sh[];
    for (int c = threadIdx.x; c < NCELLS; c += blockDim.x) sh[c] = 0u;
    __syncthreads();
    const int beg = blockIdx.x * chunk;
    const int end = min(n, beg + chunk);
    for (int i = beg + threadIdx.x; i < end; i += blockDim.x) {
        float x = pts[3 * i], y = pts[3 * i + 1], z = pts[3 * i + 2];
        atomicAdd(&sh[cell_of(x, y, z)], 1u);       // smem atomic: spread, cheap
    }
    __syncthreads();
    unsigned short* row = &g_cnt[blockIdx.x * NCELLS];
    for (int c = threadIdx.x; c < NCELLS; c += blockDim.x)
        row[c] = (unsigned short)sh[c];
}

// One thread per cell: exclusive prefix over CTAs; also per-cell totals.
__global__ void scanA_kernel(int G) {
    int c = blockIdx.x * blockDim.x + threadIdx.x;
    if (c >= NCELLS) return;
    unsigned acc = 0;
    for (int b = 0; b < G; b++) {                   // coalesced across threads
        unsigned v = g_cnt[b * NCELLS + c];
        g_offs[b * NCELLS + c] = acc;
        acc += v;
    }
    g_totals[c] = acc;
}

// Single-CTA exclusive scan over the 32768 per-cell totals -> g_base.
__global__ __launch_bounds__(1024, 1) void scanB_kernel() {
    __shared__ unsigned ssum[1024];
    const int tid = threadIdx.x;
    const int per = NCELLS / 1024;  // 32
    unsigned s = 0;
    for (int c = 0; c < per; c++) s += g_totals[tid * per + c];
    ssum[tid] = s;
    __syncthreads();
    for (int off = 1; off < 1024; off <<= 1) {
        unsigned v = (tid >= off) ? ssum[tid - off] : 0u;
        __syncthreads();
        ssum[tid] += v;
        __syncthreads();
    }
    unsigned run = (tid == 0) ? 0u : ssum[tid - 1];
    for (int c = 0; c < per; c++) {
        unsigned h = g_totals[tid * per + c];
        g_base[tid * per + c] = run;
        run += h;
    }
}

// Scatter: slot from SMEM cursors (no global atomics); one STG.128 per point.
__global__ __launch_bounds__(1024, 1)
void scatter_smem_kernel(const float* __restrict__ pts, int n, int chunk) {
    extern __shared__ unsigned cur[];
    const unsigned* offrow = &g_offs[blockIdx.x * NCELLS];
    for (int c = threadIdx.x; c < NCELLS; c += blockDim.x)
        cur[c] = g_base[c] + offrow[c];
    __syncthreads();
    const int beg = blockIdx.x * chunk;
    const int end = min(n, beg + chunk);
    for (int i = beg + threadIdx.x; i < end; i += blockDim.x) {
        float x = pts[3 * i], y = pts[3 * i + 1], z = pts[3 * i + 2];
        unsigned slot = atomicAdd(&cur[cell_of(x, y, z)], 1u);
        uint4 rec;
        rec.x = __float_as_uint(x);
        rec.y = __float_as_uint(y);
        rec.z = __float_as_uint(z);
        rec.w = (unsigned)i;
        g_sorted[slot] = rec;
    }
}

template <int LAST_RES, bool BINNED>
__global__ __launch_bounds__(THREADS, 2)
void hashgrid_kernel(const float* __restrict__ pts, Params prm,
                     float* __restrict__ out, int n)
{
    extern __shared__ uint2 scb[];   // entry: {half2(f0,f1), half2(f2,_)}

    #pragma unroll
    for (int l = 0; l < NLOD; l++) {
        const float* __restrict__ src = prm.cb[l];
        const int sz = H_SIZES(l);
        const int off = H_OFFS(l);
        for (int i = threadIdx.x; i < sz; i += THREADS) {
            __half2 h01 = __floats2half2_rn(src[3 * i], src[3 * i + 1]);
            __half2 h23 = __floats2half2_rn(src[3 * i + 2], 0.0f);
            uint2 v;
            v.x = *reinterpret_cast<unsigned*>(&h01);
            v.y = *reinterpret_cast<unsigned*>(&h23);
            scb[off + i] = v;
        }
    }
    __syncthreads();

    const int stride = gridDim.x * THREADS;
    for (int j = blockIdx.x * THREADS + threadIdx.x; j < n; j += stride) {
        float px, py, pz;
        int oi;
        if (BINNED) {
            const uint4 rec = g_sorted[j];          // one LDG.128, coalesced
            px = __uint_as_float(rec.x);
            py = __uint_as_float(rec.y);
            pz = __uint_as_float(rec.z);
            oi = (int)rec.w;
        } else {
            px = pts[3 * j + 0];
            py = pts[3 * j + 1];
            pz = pts[3 * j + 2];
            oi = j;
        }
        float a0 = 0.0f, a1 = 0.0f, a2 = 0.0f;

        #pragma unroll
        for (int l = 0; l < NLOD; l++) {
            constexpr int RESA[NLOD] = {7, 8, 11, 14, 18, 23, 30, 38, 50, LAST_RES};
            const int R = RESA[l];
            const unsigned S = (unsigned)H_SIZES(l);   // compile-time -> magic mod
            const int O = H_OFFS(l);
            const float scale = (float)(R - 1);

            const float xs = px * scale, ys = py * scale, zs = pz * scale;
            int x0 = (int)xs; x0 = x0 > R - 2 ? R - 2 : x0;
            int y0 = (int)ys; y0 = y0 > R - 2 ? R - 2 : y0;
            int z0 = (int)zs; z0 = z0 > R - 2 ? R - 2 : z0;
            const float wx = xs - (float)x0, wy = ys - (float)y0, wz = zs - (float)z0;
            const float ux = 1.0f - wx, uy = 1.0f - wy, uz = 1.0f - wz;

            const unsigned hx0 = (unsigned)x0;
            const unsigned hx1 = hx0 + 1u;
            const unsigned hy0 = (unsigned)y0 * 2654435761u;
            const unsigned hy1 = hy0 + 2654435761u;
            const unsigned hz0 = (unsigned)z0 * 805459861u;
            const unsigned hz1 = hz0 + 805459861u;

            const float w00 = uy * uz, w01 = uy * wz, w10 = wy * uz, w11 = wy * wz;

            #define HG_CORNER(HX, HY, HZ, WX, WYZ)                           \
            {                                                                \
                const unsigned idx = ((HX) ^ (HY) ^ (HZ)) % S;               \
                const uint2 v = scb[O + (int)idx];                           \
                const __half2 h01 = *reinterpret_cast<const __half2*>(&v.x); \
                const __half  h2  = *reinterpret_cast<const __half*>(&v.y);  \
                const float2 f01 = __half22float2(h01);                      \
                const float  f2  = __half2float(h2);                         \
                const float w = (WX) * (WYZ);                                \
                a0 = fmaf(w, f01.x, a0);                                     \
                a1 = fmaf(w, f01.y, a1);                                     \
                a2 = fmaf(w, f2,    a2);                                     \
            }
            HG_CORNER(hx0, hy0, hz0, ux, w00)
            HG_CORNER(hx0, hy0, hz1, ux, w01)
            HG_CORNER(hx0, hy1, hz0, ux, w10)
            HG_CORNER(hx0, hy1, hz1, ux, w11)
            HG_CORNER(hx1, hy0, hz0, wx, w00)
            HG_CORNER(hx1, hy0, hz1, wx, w01)
            HG_CORNER(hx1, hy1, hz0, wx, w10)
            HG_CORNER(hx1, hy1, hz1, wx, w11)
            #undef HG_CORNER
        }

        out[3 * oi + 0] = a0;
        out[3 * oi + 1] = a1;
        out[3 * oi + 2] = a2;
    }
}

template <int LAST_RES>
static void launch_main(bool binned, const float* pts, const Params& prm,
                        float* out, int n, int blocks)
{
    if (binned) {
        cudaFuncSetAttribute(hashgrid_kernel<LAST_RES, true>,
                             cudaFuncAttributeMaxDynamicSharedMemorySize, SMEM_BYTES);
        hashgrid_kernel<LAST_RES, true><<<blocks, THREADS, SMEM_BYTES>>>(pts, prm, out, n);
    } else {
        cudaFuncSetAttribute(hashgrid_kernel<LAST_RES, false>,
                             cudaFuncAttributeMaxDynamicSharedMemorySize, SMEM_BYTES);
        hashgrid_kernel<LAST_RES, false><<<blocks, THREADS, SMEM_BYTES>>>(pts, prm, out, n);
    }
}

extern "C" void kernel_launch(void* const* d_in, const int* in_sizes, int n_in,
                              void* d_out, int out_size)
{
    const float* pts = (const float*)d_in[0];
    const int n = in_sizes[0] / 3;

    Params prm;
    for (int l = 0; l < NLOD; l++) prm.cb[l] = (const float*)d_in[1 + l];

    // Replicate the reference's LOD formula exactly in double precision:
    // 6*b^9 sits within fp noise of exactly 64.0; compute the floor the same
    // way numpy does and dispatch on the result.
    const double b = exp((log(64.0) - log(6.0)) / 9.0);
    const double v9 = 6.0 * pow(b, 9.0);
    const int last_res = (int)(1.0 + floor(v9));

    int sm_count = 0;
    cudaDeviceGetAttribute(&sm_count, cudaDevAttrMultiProcessorCount, 0);
    if (sm_count <= 0) sm_count = 148;

    const int main_blocks = sm_count * 2;
    int G = sm_count; if (G > GMAX) G = GMAX;

    float* out = (float*)d_out;
    const bool binned = (n > 0 && n <= NMAX);

    if (binned) {
        const int chunk = (n + G - 1) / G;
        cudaFuncSetAttribute(hist_smem_kernel,
                             cudaFuncAttributeMaxDynamicSharedMemorySize, BIN_SMEM);
        cudaFuncSetAttribute(scatter_smem_kernel,
                             cudaFuncAttributeMaxDynamicSharedMemorySize, BIN_SMEM);
        hist_smem_kernel<<<G, 1024, BIN_SMEM>>>(pts, n, chunk);
        scanA_kernel<<<(NCELLS + 255) / 256, 256>>>(G);
        scanB_kernel<<<1, 1024>>>();
        scatter_smem_kernel<<<G, 1024, BIN_SMEM>>>(pts, n, chunk);
    }

    if (last_res == 65) launch_main<65>(binned, pts, prm, out, n, main_blocks);
    else                launch_main<64>(binned, pts, prm, out, n, main_blocks);
}

// round 9
// speedup vs baseline: 2.2455x; 2.0436x over previous
#include <cuda_runtime.h>
#include <cuda_fp16.h>
#include <math.h>

// HashGrid: 10-level Instant-NGP hash encoding, 2M points, FEAT_DIM=3.
// R9: revert to single-kernel R2 architecture (sort path falsified: issue
// floor ~76us independent of gather coherence, binning cost >= 90us).
// Cut the issue floor instead: smem entry = {half2(f0,f1), f32 f2} (8 B),
// comps 0/1 via HFMA2 into a per-level half2 accumulator (8 terms only),
// comp 2 via direct fp32 FFMA. Removes all per-corner converts.

#define NLOD 10

struct Params { const float* cb[NLOD]; };

// sizes = min(lod^2, 1024) for lods {7,8,11,14,18,23,30,38,50,64/65}
__host__ __device__ constexpr int H_SIZES(int l) {
    constexpr int s[NLOD] = {49, 64, 121, 196, 324, 529, 900, 1024, 1024, 1024};
    return s[l];
}
__host__ __device__ constexpr int H_OFFS(int l) {
    constexpr int o[NLOD] = {0, 49, 113, 234, 430, 754, 1283, 2183, 3207, 4231};
    return o[l];
}
constexpr int H_TOTAL = 5255;
constexpr int SMEM_BYTES = H_TOTAL * 8;   // 42,040 B (uint2 per entry)
constexpr int THREADS = 512;

template <int LAST_RES>
__global__ __launch_bounds__(THREADS, 2)
void hashgrid_kernel(const float* __restrict__ pts, Params prm,
                     float* __restrict__ out, int n)
{
    extern __shared__ uint2 scb[];   // entry: {half2(f0,f1), f32 f2}

    // ---- Stage codebooks: comps 0,1 as half2; comp 2 kept fp32 ----
    #pragma unroll
    for (int l = 0; l < NLOD; l++) {
        const float* __restrict__ src = prm.cb[l];
        const int sz = H_SIZES(l);
        const int off = H_OFFS(l);
        for (int i = threadIdx.x; i < sz; i += THREADS) {
            __half2 h01 = __floats2half2_rn(src[3 * i], src[3 * i + 1]);
            uint2 v;
            v.x = *reinterpret_cast<unsigned*>(&h01);
            v.y = __float_as_uint(src[3 * i + 2]);
            scb[off + i] = v;
        }
    }
    __syncthreads();

    const int stride = gridDim.x * THREADS;
    for (int i = blockIdx.x * THREADS + threadIdx.x; i < n; i += stride) {
        const float px = pts[3 * i + 0];
        const float py = pts[3 * i + 1];
        const float pz = pts[3 * i + 2];
        float a0 = 0.0f, a1 = 0.0f, a2 = 0.0f;

        #pragma unroll
        for (int l = 0; l < NLOD; l++) {
            constexpr int RESA[NLOD] = {7, 8, 11, 14, 18, 23, 30, 38, 50, LAST_RES};
            const int R = RESA[l];
            const unsigned S = (unsigned)H_SIZES(l);   // compile-time -> magic mod
            const int O = H_OFFS(l);
            const float scale = (float)(R - 1);

            const float xs = px * scale, ys = py * scale, zs = pz * scale;
            int x0 = (int)xs; x0 = x0 > R - 2 ? R - 2 : x0;  // xs >= 0: trunc == floor
            int y0 = (int)ys; y0 = y0 > R - 2 ? R - 2 : y0;
            int z0 = (int)zs; z0 = z0 > R - 2 ? R - 2 : z0;
            const float wx = xs - (float)x0, wy = ys - (float)y0, wz = zs - (float)z0;
            const float ux = 1.0f - wx, uy = 1.0f - wy, uz = 1.0f - wz;

            // Instant-NGP primes: {1, 2654435761, 805459861}
            const unsigned hx0 = (unsigned)x0;
            const unsigned hx1 = hx0 + 1u;
            const unsigned hy0 = (unsigned)y0 * 2654435761u;
            const unsigned hy1 = hy0 + 2654435761u;
            const unsigned hz0 = (unsigned)z0 * 805459861u;
            const unsigned hz1 = hz0 + 805459861u;

            const float w00 = uy * uz, w01 = uy * wz, w10 = wy * uz, w11 = wy * wz;

            __half2 acc01 = __float2half2_rn(0.0f);   // per-level fp16 accum (8 terms)

            #define HG_CORNER(HX, HY, HZ, WX, WYZ)                           \
            {                                                                \
                const unsigned idx = ((HX) ^ (HY) ^ (HZ)) % S;               \
                const uint2 v = scb[O + (int)idx];                           \
                const __half2 h01 = *reinterpret_cast<const __half2*>(&v.x); \
                const float w = (WX) * (WYZ);                                \
                acc01 = __hfma2(__float2half2_rn(w), h01, acc01);            \
                a2 = fmaf(w, __uint_as_float(v.y), a2);                      \
            }
            HG_CORNER(hx0, hy0, hz0, ux, w00)
            HG_CORNER(hx0, hy0, hz1, ux, w01)
            HG_CORNER(hx0, hy1, hz0, ux, w10)
            HG_CORNER(hx0, hy1, hz1, ux, w11)
            HG_CORNER(hx1, hy0, hz0, wx, w00)
            HG_CORNER(hx1, hy0, hz1, wx, w01)
            HG_CORNER(hx1, hy1, hz0, wx, w10)
            HG_CORNER(hx1, hy1, hz1, wx, w11)
            #undef HG_CORNER

            const float2 t = __half22float2(acc01);   // upconvert per level
            a0 += t.x;
            a1 += t.y;
        }

        out[3 * i + 0] = a0;
        out[3 * i + 1] = a1;
        out[3 * i + 2] = a2;
    }
}

extern "C" void kernel_launch(void* const* d_in, const int* in_sizes, int n_in,
                              void* d_out, int out_size)
{
    const float* pts = (const float*)d_in[0];
    const int n = in_sizes[0] / 3;

    Params prm;
    for (int l = 0; l < NLOD; l++) prm.cb[l] = (const float*)d_in[1 + l];

    // Replicate the reference's LOD formula exactly in double precision:
    // 6*b^9 sits within fp noise of exactly 64.0; compute the floor the same
    // way numpy does and dispatch on the result.
    const double b = exp((log(64.0) - log(6.0)) / 9.0);
    const double v9 = 6.0 * pow(b, 9.0);
    const int last_res = (int)(1.0 + floor(v9));

    int sm_count = 0;
    cudaDeviceGetAttribute(&sm_count, cudaDevAttrMultiProcessorCount, 0);
    if (sm_count <= 0) sm_count = 148;
    const int blocks = sm_count * 2;  // 2 CTAs/SM

    float* out = (float*)d_out;

    if (last_res == 65) {
        cudaFuncSetAttribute(hashgrid_kernel<65>,
                             cudaFuncAttributeMaxDynamicSharedMemorySize, SMEM_BYTES);
        hashgrid_kernel<65><<<blocks, THREADS, SMEM_BYTES>>>(pts, prm, out, n);
    } else {
        cudaFuncSetAttribute(hashgrid_kernel<64>,
                             cudaFuncAttributeMaxDynamicSharedMemorySize, SMEM_BYTES);
        hashgrid_kernel<64><<<blocks, THREADS, SMEM_BYTES>>>(pts, prm, out, n);
    }
}